// round 4
// baseline (speedup 1.0000x reference)
#include <cuda_runtime.h>

// 2D single-level DWT (L=2, Haar-style): pure 2x2 stencil per output group.
// Input : x[b][r][c], b<64, r,c<512 (f32)
// Output: 512x512 per image, quadrants [[ll, hl],[lh, hh]]
//
// R4: persistent grid-stride (1 wave, 148*8 CTAs) to remove wave-transition
// overhead; per-iteration body identical to the best (R1) mapping:
//   2x float4 loads, 4x float2 evict-first stores.

#define NBLOCKS (148 * 8)
#define NTHREADS 256
#define TOTAL_WORK (64 * 256 * 128)   // work items: b * n * t

__global__ void __launch_bounds__(NTHREADS) dwt_haar_kernel(
    const float* __restrict__ x,
    const float* __restrict__ lpf,
    const float* __restrict__ hpf,
    float* __restrict__ out)
{
    const float lo0 = __ldg(&lpf[0]);
    const float lo1 = __ldg(&lpf[1]);
    const float hi0 = __ldg(&hpf[0]);
    const float hi1 = __ldg(&hpf[1]);

    const int stride = NBLOCKS * NTHREADS;

    for (int gid = blockIdx.x * NTHREADS + threadIdx.x; gid < TOTAL_WORK; gid += stride) {
        const int t = gid & 127;          // width-pair index (2 output cols)
        const int n = (gid >> 7) & 255;   // subband row
        const int b = gid >> 15;          // batch

        const long long img = (long long)b * (512 * 512);
        const float* p0 = x + img + (long long)(2 * n) * 512 + 4 * t;

        const float4 r0 = *reinterpret_cast<const float4*>(p0);
        const float4 r1 = *reinterpret_cast<const float4*>(p0 + 512);

        float2 ll, lh, hl, hh;
        {
            float at = lo0 * r0.x + lo1 * r0.y, ab = lo0 * r1.x + lo1 * r1.y;
            float dt = hi0 * r0.x + hi1 * r0.y, db = hi0 * r1.x + hi1 * r1.y;
            ll.x = lo0 * at + lo1 * ab;  lh.x = hi0 * at + hi1 * ab;
            hl.x = lo0 * dt + lo1 * db;  hh.x = hi0 * dt + hi1 * db;
        }
        {
            float at = lo0 * r0.z + lo1 * r0.w, ab = lo0 * r1.z + lo1 * r1.w;
            float dt = hi0 * r0.z + hi1 * r0.w, db = hi0 * r1.z + hi1 * r1.w;
            ll.y = lo0 * at + lo1 * ab;  lh.y = hi0 * at + hi1 * ab;
            hl.y = lo0 * dt + lo1 * db;  hh.y = hi0 * dt + hi1 * db;
        }

        const int m = 2 * t;
        float* o_ll = out + img + (long long)n * 512 + m;
        float* o_lh = out + img + (long long)(n + 256) * 512 + m;

        // Evict-first: keep the input L2-resident across graph replays.
        __stcs(reinterpret_cast<float2*>(o_ll),       ll);
        __stcs(reinterpret_cast<float2*>(o_ll + 256), hl);
        __stcs(reinterpret_cast<float2*>(o_lh),       lh);
        __stcs(reinterpret_cast<float2*>(o_lh + 256), hh);
    }
}

extern "C" void kernel_launch(void* const* d_in, const int* in_sizes, int n_in,
                              void* d_out, int out_size)
{
    const float* x   = (const float*)d_in[0];
    const float* lpf = (const float*)d_in[1];
    const float* hpf = (const float*)d_in[2];
    float* out = (float*)d_out;

    dwt_haar_kernel<<<NBLOCKS, NTHREADS>>>(x, lpf, hpf, out);
}